// round 4
// baseline (speedup 1.0000x reference)
#include <cuda_runtime.h>

// T=4 LIF over repeated input.
// in:  (B=32, L=720, C=862) f32
// out: (T=4, B=32, C=862, L=720) f32 spikes
// Per element: v=0; 4x { v=(v+x)/2; s=(v>=1); if(s) v=0; }
// HBM-bound: 79.4MB read + 317.8MB write.
//
// R4: persistent grid (1216 blocks = 152 SMs x occ8), double-buffered smem,
// software pipeline: prefetch tile i+1 (LDG->regs) | write tile i | STS -> buf^1.
// One __syncthreads per tile. Removes wave-transition + per-block read bubbles.

#define L_DIM 720
#define C_DIM 862
#define B_DIM 32
#define T_STEPS 4
#define TILE 32
#define NT_C 27                       // ceil(862/32)
#define NT_L 23                       // ceil(720/32)
#define NUM_TILES (NT_C * NT_L * B_DIM)   // 19872
#define GRID_BLOCKS (152 * 8)

__device__ __forceinline__ void decode_tile(int t, int& b, int& lBase, int& cBase) {
    int cx = t % NT_C;
    int r  = t / NT_C;
    int ly = r % NT_L;
    b      = r / NT_L;
    lBase = ly * TILE;
    cBase = cx * TILE;
}

__device__ __forceinline__ void load_tile(const float* __restrict__ in,
                                          int t, int tx, int ty, float pf[4]) {
    int b, lBase, cBase;
    decode_tile(t, b, lBase, cBase);
    const float* inb = in + (size_t)b * ((size_t)L_DIM * C_DIM);
    const int c_in = cBase + tx;
#pragma unroll
    for (int k = 0; k < 4; k++) {
        int l = lBase + ty + k * 8;
        pf[k] = (c_in < C_DIM && l < L_DIM) ? __ldg(inb + (size_t)l * C_DIM + c_in)
                                            : 0.0f;
    }
}

__global__ __launch_bounds__(256, 8)
void lif_transpose_kernel(const float* __restrict__ in, float* __restrict__ out) {
    __shared__ float buf[2][TILE][TILE + 1];

    const int tid = threadIdx.x;
    const int tx  = tid & 31;   // load-role: c lane
    const int ty  = tid >> 5;   // load-role: l group
    // write-role:
    const int c_local = tid >> 3;   // 0..31
    const int l4      = tid & 7;    // 0..7
    const size_t plane = (size_t)B_DIM * C_DIM * L_DIM;

    int t = blockIdx.x;
    if (t >= NUM_TILES) return;

    // prologue: fill buffer 0
    {
        float pf[4];
        load_tile(in, t, tx, ty, pf);
#pragma unroll
        for (int k = 0; k < 4; k++) buf[0][ty + k * 8][tx] = pf[k];
    }
    __syncthreads();

    int p = 0;
    while (true) {
        const int tn = t + GRID_BLOCKS;
        float pf[4];
        const bool have_next = (tn < NUM_TILES);
        if (have_next) load_tile(in, tn, tx, ty, pf);   // LDGs in flight

        // ---- write phase for tile t from buf[p] ----
        int b, lBase, cBase;
        decode_tile(t, b, lBase, cBase);
        const int c = cBase + c_local;
        const int l = lBase + l4 * 4;
        if (c < C_DIM && l < L_DIM) {
            float sv[T_STEPS][4];
#pragma unroll
            for (int j = 0; j < 4; j++) {
                float x = buf[p][l4 * 4 + j][c_local];
                float v = 0.0f;
#pragma unroll
                for (int ts = 0; ts < T_STEPS; ts++) {
                    v = (v + x) * 0.5f;
                    bool fire = (v >= 1.0f);
                    sv[ts][j] = fire ? 1.0f : 0.0f;
                    v = fire ? 0.0f : v;
                }
            }
            float* obase = out + (size_t)b * ((size_t)C_DIM * L_DIM)
                               + (size_t)c * L_DIM + l;
#pragma unroll
            for (int ts = 0; ts < T_STEPS; ts++) {
                float4 v4 = make_float4(sv[ts][0], sv[ts][1], sv[ts][2], sv[ts][3]);
                __stcs(reinterpret_cast<float4*>(obase + ts * plane), v4);
            }
        }

        if (!have_next) break;

        // stage next tile into the other buffer
#pragma unroll
        for (int k = 0; k < 4; k++) buf[p ^ 1][ty + k * 8][tx] = pf[k];
        __syncthreads();
        p ^= 1;
        t = tn;
    }
}

extern "C" void kernel_launch(void* const* d_in, const int* in_sizes, int n_in,
                              void* d_out, int out_size) {
    const float* in = (const float*)d_in[0];
    float* out = (float*)d_out;
    lif_transpose_kernel<<<GRID_BLOCKS, 256>>>(in, out);
}

// round 5
// speedup vs baseline: 1.1248x; 1.1248x over previous
#include <cuda_runtime.h>

// T=4 LIF over repeated input.
// in:  (B=32, L=720, C=862) f32  ->  out: (T=4, B=32, C=862, L=720) f32 spikes
// Per element: v=0; 4x { v=(v+x)/2; s=(v>=1); if(s) v=0; }
// HBM-bound: 79.4MB read + 317.8MB write. Limiter = DRAM read/write turnaround.
//
// R5: 64x64 tiles, 512 threads. Bigger per-block read-phase / write-phase bursts
// to coarsen the chip-wide read/write mix at the HBM controller. Write pattern
// per warp unchanged from R1 (full-line float4 stores, warp-parallel).

#define L_DIM 720
#define C_DIM 862
#define B_DIM 32
#define T_STEPS 4
#define TILE 64

__global__ __launch_bounds__(512, 4)
void lif_transpose_kernel(const float* __restrict__ in, float* __restrict__ out) {
    __shared__ float tile[TILE][TILE + 1];

    const int b     = blockIdx.z;
    const int lBase = blockIdx.y * TILE;
    const int cBase = blockIdx.x * TILE;
    const int tid = threadIdx.x;

    // ---- load phase: scalar, coalesced along C. tx=c lane (0..63), ty=row group ----
    {
        const int tx = tid & 63;
        const int ty = tid >> 6;   // 0..7
        const float* inb = in + (size_t)b * ((size_t)L_DIM * C_DIM);
        const int c_in = cBase + tx;
        if (c_in < C_DIM) {
#pragma unroll
            for (int k = 0; k < 8; k++) {
                int ll = ty + k * 8;
                int l  = lBase + ll;
                if (l < L_DIM)
                    tile[ll][tx] = inb[(size_t)l * C_DIM + c_in];
            }
        }
    }
    __syncthreads();

    // ---- write phase: lane group of 16 covers one c-row's 64 l's (256B contiguous);
    //      2 passes over c. Full-line float4 stores, 4 planes. ----
    const int l4      = tid & 15;        // 0..15 -> l_local = 4*l4
    const int c_base_local = tid >> 4;   // 0..31
    const int l = lBase + l4 * 4;
    if (l >= L_DIM) return;              // L_DIM % 4 == 0: float4 all-or-nothing

    const size_t plane = (size_t)B_DIM * C_DIM * L_DIM;
    float* ob = out + (size_t)b * ((size_t)C_DIM * L_DIM) + l;

#pragma unroll
    for (int pass = 0; pass < 2; pass++) {
        const int c_local = c_base_local + pass * 32;
        const int c = cBase + c_local;
        if (c >= C_DIM) continue;

        float sv[T_STEPS][4];
#pragma unroll
        for (int j = 0; j < 4; j++) {
            float x = tile[l4 * 4 + j][c_local];
            float v = 0.0f;
#pragma unroll
            for (int t = 0; t < T_STEPS; t++) {
                v = (v + x) * 0.5f;
                bool fire = (v >= 1.0f);
                sv[t][j] = fire ? 1.0f : 0.0f;
                v = fire ? 0.0f : v;
            }
        }

        float* orow = ob + (size_t)c * L_DIM;
#pragma unroll
        for (int t = 0; t < T_STEPS; t++) {
            float4 v4 = make_float4(sv[t][0], sv[t][1], sv[t][2], sv[t][3]);
            __stcs(reinterpret_cast<float4*>(orow + t * plane), v4);
        }
    }
}

extern "C" void kernel_launch(void* const* d_in, const int* in_sizes, int n_in,
                              void* d_out, int out_size) {
    const float* in = (const float*)d_in[0];
    float* out = (float*)d_out;
    dim3 grid((C_DIM + TILE - 1) / TILE,   // 14
              (L_DIM + TILE - 1) / TILE,   // 12
              B_DIM);                      // 32  -> 5376 blocks
    lif_transpose_kernel<<<grid, 512>>>(in, out);
}